// round 5
// baseline (speedup 1.0000x reference)
#include <cuda_runtime.h>
#include <cstdint>

// Problem constants (fixed by the reference)
#define BB   32
#define CC   128
#define HH   128
#define WW   128
#define OH   64
#define OW   64
// output plane stride (vals / pos_h / pos_w planes), in elements
#define PLANE (CC * OH * OW)   // 524288

__device__ __forceinline__ void win2x2(float a, float b, float c, float d,
                                       int row0, int col0,
                                       float& val, float& ph, float& pw) {
    // first-max argmax over order [a, b, c, d] == flat idx kh*2+kw
    float best = a; int idx = 0;
    if (b > best) { best = b; idx = 1; }
    if (c > best) { best = c; idx = 2; }
    if (d > best) { best = d; idx = 3; }
    int row = row0 + (idx >> 1);
    int col = col0 + (idx & 1);
    val = best;
    ph = (float)row * (1.0f / (float)HH);
    pw = (float)col * (1.0f / (float)WW);
}

__global__ void __launch_bounds__(256)
pap_pool_kernel(const float* __restrict__ x, float* __restrict__ out) {
    // One WARP owns: one bc, FOUR output rows (8 input rows).
    // Lane l loads float4 at column 4*l of each of the 8 input rows:
    // every LDG.128 is 32 lanes x 16B = 512B fully contiguous (warp-strided).
    // Per-warp: 8 front-batched reads (4KB burst), 12 back-batched writes (3KB).
    // total warps = B*C*(OH/4) = 4096*16 = 65536 -> 2,097,152 threads.
    unsigned tid  = blockIdx.x * blockDim.x + threadIdx.x;
    unsigned lane = tid & 31u;
    unsigned w    = tid >> 5;

    unsigned ohq = w & 15u;    // output-row quad index, 0..15
    unsigned bc  = w >> 4;     // b*C + c, 0..4095

    // input rows 8*ohq .. 8*ohq+7 of channel bc
    const float4* p = reinterpret_cast<const float4*>(
        x + bc * (HH * WW) + (8u * ohq) * WW) + lane;

    // front-batch 8 perfectly-coalesced loads (512B/instr, MLP=8)
    float4 r0 = p[0];
    float4 r1 = p[32];
    float4 r2 = p[64];
    float4 r3 = p[96];
    float4 r4 = p[128];
    float4 r5 = p[160];
    float4 r6 = p[192];
    float4 r7 = p[224];

    int row0 = 8 * (int)ohq;
    int col0 = 4 * (int)lane;

    float v[8], ph[8], pw[8];   // [out_row 0..3][col pair 0..1] flattened 2*r+j
    win2x2(r0.x, r0.y, r1.x, r1.y, row0,     col0,     v[0], ph[0], pw[0]);
    win2x2(r0.z, r0.w, r1.z, r1.w, row0,     col0 + 2, v[1], ph[1], pw[1]);
    win2x2(r2.x, r2.y, r3.x, r3.y, row0 + 2, col0,     v[2], ph[2], pw[2]);
    win2x2(r2.z, r2.w, r3.z, r3.w, row0 + 2, col0 + 2, v[3], ph[3], pw[3]);
    win2x2(r4.x, r4.y, r5.x, r5.y, row0 + 4, col0,     v[4], ph[4], pw[4]);
    win2x2(r4.z, r4.w, r5.z, r5.w, row0 + 4, col0 + 2, v[5], ph[5], pw[5]);
    win2x2(r6.x, r6.y, r7.x, r7.y, row0 + 6, col0,     v[6], ph[6], pw[6]);
    win2x2(r6.z, r6.w, r7.z, r7.w, row0 + 6, col0 + 2, v[7], ph[7], pw[7]);

    // output: [B, 3C, OH, OW]; b = bc/128, c = bc%128
    unsigned b = bc >> 7;
    unsigned c = bc & 127u;
    unsigned oh0 = 4u * ohq;
    float* o = out + ((b * 3u * CC + c) * OH + oh0) * OW + 2u * lane;

    // 12 STG.64, each 32 lanes x 8B = 256B contiguous; rows adjacent -> long write runs
    *reinterpret_cast<float2*>(o + 0 * OW)             = make_float2(v[0], v[1]);
    *reinterpret_cast<float2*>(o + 1 * OW)             = make_float2(v[2], v[3]);
    *reinterpret_cast<float2*>(o + 2 * OW)             = make_float2(v[4], v[5]);
    *reinterpret_cast<float2*>(o + 3 * OW)             = make_float2(v[6], v[7]);
    *reinterpret_cast<float2*>(o + PLANE + 0 * OW)     = make_float2(ph[0], ph[1]);
    *reinterpret_cast<float2*>(o + PLANE + 1 * OW)     = make_float2(ph[2], ph[3]);
    *reinterpret_cast<float2*>(o + PLANE + 2 * OW)     = make_float2(ph[4], ph[5]);
    *reinterpret_cast<float2*>(o + PLANE + 3 * OW)     = make_float2(ph[6], ph[7]);
    *reinterpret_cast<float2*>(o + 2 * PLANE + 0 * OW) = make_float2(pw[0], pw[1]);
    *reinterpret_cast<float2*>(o + 2 * PLANE + 1 * OW) = make_float2(pw[2], pw[3]);
    *reinterpret_cast<float2*>(o + 2 * PLANE + 2 * OW) = make_float2(pw[4], pw[5]);
    *reinterpret_cast<float2*>(o + 2 * PLANE + 3 * OW) = make_float2(pw[6], pw[7]);
}

extern "C" void kernel_launch(void* const* d_in, const int* in_sizes, int n_in,
                              void* d_out, int out_size) {
    const float* x = (const float*)d_in[0];
    float* out = (float*)d_out;
    // 2,097,152 threads total
    const unsigned nthreads = BB * CC * (OH / 4) * 32;
    const unsigned block = 256;
    pap_pool_kernel<<<nthreads / block, block>>>(x, out);
}